// round 16
// baseline (speedup 1.0000x reference)
#include <cuda_runtime.h>
#include <cuda_fp16.h>
#include <cstdint>

#define E_DIM 256
#define MQ (64*8*128)     /* 65536 query tokens  */
#define MC (2*MQ)         /* 131072 constant rows */

// ---------------- scratch (allocation-free: __device__ globals) ----------------
__device__ __half g_Qh [(size_t)MQ*E_DIM];
__device__ __half g_Kh [(size_t)MC*E_DIM];
__device__ __half g_Vh [(size_t)MC*E_DIM];
__device__ __half g_WSh[(size_t)MQ*E_DIM];
__device__ __half g_Wf[4][E_DIM*E_DIM];

// 128B-row swizzle (rows of 64 fp16 = 128B).
__device__ __forceinline__ int swb(int byte){
  return byte ^ ((byte >> 3) & 0x70);
}

__device__ __forceinline__ void ldm4(uint32_t addr, uint32_t r[4]){
  asm volatile("ldmatrix.sync.aligned.m8n8.x4.shared.b16 {%0,%1,%2,%3}, [%4];\n"
    : "=r"(r[0]),"=r"(r[1]),"=r"(r[2]),"=r"(r[3]) : "r"(addr));
}

__device__ __forceinline__ void mma16816(float c[4], const uint32_t a[4],
                                         uint32_t b0, uint32_t b1){
  asm volatile("mma.sync.aligned.m16n8k16.row.col.f32.f16.f16.f32 "
    "{%0,%1,%2,%3}, {%4,%5,%6,%7}, {%8,%9}, {%0,%1,%2,%3};\n"
    : "+f"(c[0]),"+f"(c[1]),"+f"(c[2]),"+f"(c[3])
    : "r"(a[0]),"r"(a[1]),"r"(a[2]),"r"(a[3]), "r"(b0),"r"(b1));
}

__device__ __forceinline__ void cp_async16(uint32_t dst, const void* src){
  asm volatile("cp.async.cg.shared.global [%0], [%1], 16;" :: "r"(dst), "l"(src));
}
#define CP_COMMIT() asm volatile("cp.async.commit_group;" ::: "memory")
#define CP_WAIT1()  asm volatile("cp.async.wait_group 1;" ::: "memory")
#define CP_WAIT0()  asm volatile("cp.async.wait_group 0;" ::: "memory")

// ---------------- weight fp16 prep ----------------
__global__ void prep_weights(const float* __restrict__ Wq, const float* __restrict__ Wk,
                             const float* __restrict__ Wv, const float* __restrict__ Wo){
  int i = blockIdx.x * blockDim.x + threadIdx.x;   // 0 .. 65535
  const float* src[4] = {Wq, Wk, Wv, Wo};
#pragma unroll
  for (int w = 0; w < 4; w++){
    g_Wf[w][i] = __float2half_rn(src[w][i]);
  }
}

// Shared tile geometry: CTA 128x256, 512 threads, 16 warps (64x32), BK=64,
// 3-stage cp.async pipeline, double-buffered register fragments.
// stage: A 128x64 (16K) + B 256x64 (32K) = 48KB; x3 = 144KB dynamic.
#define ST_A 16384
#define ST_B 32768
#define STAGE (ST_A + ST_B)
#define SMEM_TOT (3*STAGE)

// ============ PHASE 0: Q/K/V projections (A fp32 -> fp16 convert) =============
__global__ void __launch_bounds__(512, 1)
gemm_qkv(const float* __restrict__ p, const float* __restrict__ c,
         const float* __restrict__ bq, const float* __restrict__ bk,
         const float* __restrict__ bv)
{
  extern __shared__ __align__(128) char smem[];

  const int job = (int)blockIdx.x;
  const float* __restrict__ Xf;
  const __half* __restrict__ Wm;
  __half* __restrict__ Yh;
  const float* __restrict__ bias;
  size_t mBase;
  if (job < 512){
    Xf = p;  Wm = g_Wf[0]; Yh = g_Qh; bias = bq; mBase = (size_t)job * 128;
  } else {
    const int j = job - 512;               // K/V adjacent per M-tile
    Xf = c;  mBase = (size_t)(j >> 1) * 128;
    if ((j & 1) == 0){ Wm = g_Wf[1]; Yh = g_Kh; bias = bk; }
    else             { Wm = g_Wf[2]; Yh = g_Vh; bias = bv; }
  }

  const int tid  = threadIdx.x;
  const int lane = tid & 31;
  const int warp = tid >> 5;         // 0..15
  const int wm   = warp & 1;         // rows wm*64
  const int wn   = warp >> 1;        // cols wn*32 (0..7)

  auto issueAsync = [&](int kk, int s){
    char* st = smem + s * STAGE;
#pragma unroll
    for (int i = 0; i < 4; i++){
      int id = tid + i*512;                   // 0..2047
      int row = id >> 3, c8 = (id & 7) * 8;
      uint32_t d = (uint32_t)__cvta_generic_to_shared(st + ST_A + swb(row*128 + c8*2));
      cp_async16(d, Wm + (size_t)row*E_DIM + kk + c8);
    }
    CP_COMMIT();
  };

  float4 ra[2];
  auto loadAh = [&](int kk, int h){
#pragma unroll
    for (int i = 0; i < 2; i++){
      int id = tid + i*512 + h*1024;
      int row = id >> 4, c4 = id & 15;
      ra[i] = *reinterpret_cast<const float4*>(Xf + (mBase + row)*E_DIM + kk + c4*4);
    }
  };
  auto storeAh = [&](int s, int h){
    char* st = smem + s * STAGE;
#pragma unroll
    for (int i = 0; i < 2; i++){
      int id = tid + i*512 + h*1024;
      int row = id >> 4, c4 = id & 15;
      float4 v = ra[i];
      __half2 h0 = __float22half2_rn(make_float2(v.x, v.y));
      __half2 h1 = __float22half2_rn(make_float2(v.z, v.w));
      int b0 = swb(row*128 + c4*8);
      *reinterpret_cast<__half2*>(st + b0)     = h0;
      *reinterpret_cast<__half2*>(st + b0 + 4) = h1;
    }
  };

  auto ldsmA = [&](char* sAc, int ks, uint32_t Af[4][4]){
#pragma unroll
    for (int mt = 0; mt < 4; mt++){
      int row = wm*64 + mt*16 + (lane & 7) + ((lane & 8) ? 8 : 0);
      int col = ks + ((lane & 16) ? 8 : 0);
      ldm4((uint32_t)__cvta_generic_to_shared(sAc + swb(row*128 + col*2)), Af[mt]);
    }
  };
  auto ldsmB = [&](char* sBc, int ks, uint32_t Bf[2][4]){
#pragma unroll
    for (int bt = 0; bt < 2; bt++){
      int row = wn*32 + bt*16 + (lane & 7) + ((lane & 8) ? 8 : 0);
      int col = ks + ((lane & 16) ? 8 : 0);
      ldm4((uint32_t)__cvta_generic_to_shared(sBc + swb(row*128 + col*2)), Bf[bt]);
    }
  };

  float acc[4][4][4];   // warp 64x32: [mt][nt][4]
#pragma unroll
  for (int i=0;i<4;i++)
#pragma unroll
    for (int j=0;j<4;j++)
#pragma unroll
      for (int k=0;k<4;k++) acc[i][j][k] = 0.f;

  issueAsync(0, 0);
  loadAh(0, 0); storeAh(0, 0);
  loadAh(0, 1); storeAh(0, 1);
  issueAsync(64, 1);

  uint32_t Af[2][4][4], Bf[2][2][4];

  for (int kc = 0; kc < 4; kc++){
    const int curS = kc % 3;
    if (kc < 3) CP_WAIT1(); else CP_WAIT0();
    __syncthreads();

    if (kc < 2) issueAsync((kc+2)*64, (kc+2) % 3);
    const int ns = (kc+1) % 3;
    const bool preA = (kc < 3);

    char* sAc = smem + curS * STAGE;
    char* sBc = sAc + ST_A;

    ldsmA(sAc, 0, Af[0]);
    ldsmB(sBc, 0, Bf[0]);
#pragma unroll
    for (int ks2 = 0; ks2 < 4; ks2++){
      const int cur = ks2 & 1, nxt = cur ^ 1;
      if (ks2 < 3){
        ldsmA(sAc, (ks2+1)*16, Af[nxt]);
        ldsmB(sBc, (ks2+1)*16, Bf[nxt]);
      }
#pragma unroll
      for (int mt=0; mt<4; mt++)
#pragma unroll
        for (int nt=0; nt<4; nt++){
          const int bt = nt >> 1, od = nt & 1;
          mma16816(acc[mt][nt], Af[cur][mt], Bf[cur][bt][od], Bf[cur][bt][2+od]);
        }
      if (preA){
        if      (ks2 == 0){ loadAh((kc+1)*64, 0); }
        else if (ks2 == 1){ storeAh(ns, 0); loadAh((kc+1)*64, 1); }
        else if (ks2 == 2){ storeAh(ns, 1); }
      }
    }
  }

  // epilogue: +bias, fp16 stores
#pragma unroll
  for (int mt=0; mt<4; mt++){
#pragma unroll
    for (int nt=0; nt<4; nt++){
      size_t m = mBase + wm*64 + mt*16 + (lane>>2);
      int    n = wn*32 + nt*8 + (lane&3)*2;
      float b0 = bias[n], b1 = bias[n+1];
      float* a = acc[mt][nt];
      *reinterpret_cast<__half2*>(Yh + m*E_DIM + n)     = __floats2half2_rn(a[0]+b0, a[1]+b1);
      *reinterpret_cast<__half2*>(Yh + (m+8)*E_DIM + n) = __floats2half2_rn(a[2]+b0, a[3]+b1);
    }
  }
}

// ============ PHASE 1: O GEMM (same structure; A fp16 via cp.async) ===========
__global__ void __launch_bounds__(512, 1)
gemm_o(const float* __restrict__ bo, float* __restrict__ out)
{
  extern __shared__ __align__(128) char smem[];

  const int job = (int)blockIdx.x;        // 512 M-tiles, full N=256 per CTA
  const __half* __restrict__ Wm = g_Wf[3];
  const size_t mBase = (size_t)job * 128;

  const int tid  = threadIdx.x;
  const int lane = tid & 31;
  const int warp = tid >> 5;         // 0..15
  const int wm   = warp & 1;         // rows wm*64
  const int wn   = warp >> 1;        // cols wn*32 (0..7)

  auto issueAsync = [&](int kk, int s){
    char* st = smem + s * STAGE;
#pragma unroll
    for (int i = 0; i < 2; i++){     // A: 1024 x 16B
      int id = tid + i*512;
      int row = id >> 3, c8 = (id & 7) * 8;
      uint32_t d = (uint32_t)__cvta_generic_to_shared(st + swb(row*128 + c8*2));
      cp_async16(d, g_WSh + (mBase + row)*E_DIM + kk + c8);
    }
#pragma unroll
    for (int i = 0; i < 4; i++){     // B: 2048 x 16B
      int id = tid + i*512;
      int row = id >> 3, c8 = (id & 7) * 8;
      uint32_t d = (uint32_t)__cvta_generic_to_shared(st + ST_A + swb(row*128 + c8*2));
      cp_async16(d, Wm + (size_t)row*E_DIM + kk + c8);
    }
    CP_COMMIT();
  };

  auto ldsmA = [&](char* sAc, int ks, uint32_t Af[4][4]){
#pragma unroll
    for (int mt = 0; mt < 4; mt++){
      int row = wm*64 + mt*16 + (lane & 7) + ((lane & 8) ? 8 : 0);
      int col = ks + ((lane & 16) ? 8 : 0);
      ldm4((uint32_t)__cvta_generic_to_shared(sAc + swb(row*128 + col*2)), Af[mt]);
    }
  };
  auto ldsmB = [&](char* sBc, int ks, uint32_t Bf[2][4]){
#pragma unroll
    for (int bt = 0; bt < 2; bt++){
      int row = wn*32 + bt*16 + (lane & 7) + ((lane & 8) ? 8 : 0);
      int col = ks + ((lane & 16) ? 8 : 0);
      ldm4((uint32_t)__cvta_generic_to_shared(sBc + swb(row*128 + col*2)), Bf[bt]);
    }
  };

  float acc[4][4][4];
#pragma unroll
  for (int i=0;i<4;i++)
#pragma unroll
    for (int j=0;j<4;j++)
#pragma unroll
      for (int k=0;k<4;k++) acc[i][j][k] = 0.f;

  issueAsync(0, 0);
  issueAsync(64, 1);

  uint32_t Af[2][4][4], Bf[2][2][4];

  for (int kc = 0; kc < 4; kc++){
    const int curS = kc % 3;
    if (kc < 3) CP_WAIT1(); else CP_WAIT0();
    __syncthreads();

    if (kc < 2) issueAsync((kc+2)*64, (kc+2) % 3);

    char* sAc = smem + curS * STAGE;
    char* sBc = sAc + ST_A;

    ldsmA(sAc, 0, Af[0]);
    ldsmB(sBc, 0, Bf[0]);
#pragma unroll
    for (int ks2 = 0; ks2 < 4; ks2++){
      const int cur = ks2 & 1, nxt = cur ^ 1;
      if (ks2 < 3){
        ldsmA(sAc, (ks2+1)*16, Af[nxt]);
        ldsmB(sBc, (ks2+1)*16, Bf[nxt]);
      }
#pragma unroll
      for (int mt=0; mt<4; mt++)
#pragma unroll
        for (int nt=0; nt<4; nt++){
          const int bt = nt >> 1, od = nt & 1;
          mma16816(acc[mt][nt], Af[cur][mt], Bf[cur][bt][od], Bf[cur][bt][2+od]);
        }
    }
  }

  // epilogue: +bias, fp32 stores
#pragma unroll
  for (int mt=0; mt<4; mt++){
#pragma unroll
    for (int nt=0; nt<4; nt++){
      size_t m = mBase + wm*64 + mt*16 + (lane>>2);
      int    n = wn*32 + nt*8 + (lane&3)*2;
      float b0 = bo[n], b1 = bo[n+1];
      float* a = acc[mt][nt];
      *reinterpret_cast<float2*>(out + m*E_DIM + n)     = make_float2(a[0]+b0, a[1]+b1);
      *reinterpret_cast<float2*>(out + (m+8)*E_DIM + n) = make_float2(a[2]+b0, a[3]+b1);
    }
  }
}

// ---------------- attention: warp per token, fp32 math on fp16 data ------------
__device__ __forceinline__ float dot8(uint4 a, uint4 b){
  const __half2* ah = reinterpret_cast<const __half2*>(&a);
  const __half2* bh = reinterpret_cast<const __half2*>(&b);
  float s = 0.f;
#pragma unroll
  for (int i = 0; i < 4; i++){
    float2 af = __half22float2(ah[i]);
    float2 bf = __half22float2(bh[i]);
    s += af.x*bf.x + af.y*bf.y;
  }
  return s;
}

__global__ void __launch_bounds__(256)
attn_kernel()
{
  const int gw   = (blockIdx.x * 256 + threadIdx.x) >> 5;  // token id
  const int lane = threadIdx.x & 31;                        // 8 lanes per head

  const uint4* q  = reinterpret_cast<const uint4*>(g_Qh + (size_t)gw*E_DIM);
  const uint4* k0 = reinterpret_cast<const uint4*>(g_Kh + (size_t)(2*gw  )*E_DIM);
  const uint4* k1 = reinterpret_cast<const uint4*>(g_Kh + (size_t)(2*gw+1)*E_DIM);
  const uint4* v0 = reinterpret_cast<const uint4*>(g_Vh + (size_t)(2*gw  )*E_DIM);
  const uint4* v1 = reinterpret_cast<const uint4*>(g_Vh + (size_t)(2*gw+1)*E_DIM);
  uint4*       ws = reinterpret_cast<uint4*>(g_WSh + (size_t)gw*E_DIM);

  uint4 qa = q[lane];
  float s0 = dot8(qa, k0[lane]);
  float s1 = dot8(qa, k1[lane]);

#pragma unroll
  for (int off = 4; off > 0; off >>= 1){            // reduce within 8-lane head group
    s0 += __shfl_xor_sync(0xffffffffu, s0, off);
    s1 += __shfl_xor_sync(0xffffffffu, s1, off);
  }
  s0 *= 0.125f;  s1 *= 0.125f;                       // 1/sqrt(D), D=64
  float mx = fmaxf(s0, s1);
  float e0 = __expf(s0 - mx), e1 = __expf(s1 - mx);
  float inv = 1.0f / (e0 + e1);
  float w0 = e0 * inv, w1 = e1 * inv;

  uint4 va = v0[lane], vb = v1[lane];
  const __half2* vah = reinterpret_cast<const __half2*>(&va);
  const __half2* vbh = reinterpret_cast<const __half2*>(&vb);
  uint4 o;
  __half2* oh = reinterpret_cast<__half2*>(&o);
#pragma unroll
  for (int i = 0; i < 4; i++){
    float2 a = __half22float2(vah[i]);
    float2 b = __half22float2(vbh[i]);
    oh[i] = __floats2half2_rn(w0*a.x + w1*b.x, w0*a.y + w1*b.y);
  }
  ws[lane] = o;
}

// ---------------- launch ----------------
extern "C" void kernel_launch(void* const* d_in, const int* in_sizes, int n_in,
                              void* d_out, int out_size)
{
  const float* p  = (const float*)d_in[0];  // (B,S,A,1,E)  -> [65536,256]
  const float* c  = (const float*)d_in[1];  // (B,S,A,2,E)  -> [131072,256]
  const float* Wq = (const float*)d_in[2];
  const float* bq = (const float*)d_in[3];
  const float* Wk = (const float*)d_in[4];
  const float* bk = (const float*)d_in[5];
  const float* Wv = (const float*)d_in[6];
  const float* bv = (const float*)d_in[7];
  const float* Wo = (const float*)d_in[8];
  const float* bo = (const float*)d_in[9];
  float* out = (float*)d_out;

  cudaFuncSetAttribute(gemm_qkv, cudaFuncAttributeMaxDynamicSharedMemorySize, SMEM_TOT);
  cudaFuncSetAttribute(gemm_o,   cudaFuncAttributeMaxDynamicSharedMemorySize, SMEM_TOT);

  prep_weights<<<256, 256>>>(Wq, Wk, Wv, Wo);
  // merged Q/K/V: 512 Q jobs + 2048 KV jobs (128x256 tiles, 512 threads)
  gemm_qkv<<<2560, 512, SMEM_TOT>>>(p, c, bq, bk, bv);
  attn_kernel<<<MQ/8, 256>>>();
  // out = WS @ Wo^T + bo (128x256 tiles, 512 threads, frag-double-buffered)
  gemm_o<<<512, 512, SMEM_TOT>>>(bo, out);
}

// round 17
// speedup vs baseline: 1.0694x; 1.0694x over previous
#include <cuda_runtime.h>
#include <cuda_fp16.h>
#include <cstdint>

#define E_DIM 256
#define MQ (64*8*128)     /* 65536 query tokens  */
#define MC (2*MQ)         /* 131072 constant rows */

// ---------------- scratch (allocation-free: __device__ globals) ----------------
__device__ __half g_Qh [(size_t)MQ*E_DIM];
__device__ __half g_Kh [(size_t)MC*E_DIM];
__device__ __half g_Vh [(size_t)MC*E_DIM];
__device__ __half g_WSh[(size_t)MQ*E_DIM];
__device__ __half g_Wf[4][E_DIM*E_DIM];

// 128B-row swizzle (rows of 64 fp16 = 128B).
__device__ __forceinline__ int swb(int byte){
  return byte ^ ((byte >> 3) & 0x70);
}

__device__ __forceinline__ void ldm4(uint32_t addr, uint32_t r[4]){
  asm volatile("ldmatrix.sync.aligned.m8n8.x4.shared.b16 {%0,%1,%2,%3}, [%4];\n"
    : "=r"(r[0]),"=r"(r[1]),"=r"(r[2]),"=r"(r[3]) : "r"(addr));
}

__device__ __forceinline__ void mma16816(float c[4], const uint32_t a[4],
                                         uint32_t b0, uint32_t b1){
  asm volatile("mma.sync.aligned.m16n8k16.row.col.f32.f16.f16.f32 "
    "{%0,%1,%2,%3}, {%4,%5,%6,%7}, {%8,%9}, {%0,%1,%2,%3};\n"
    : "+f"(c[0]),"+f"(c[1]),"+f"(c[2]),"+f"(c[3])
    : "r"(a[0]),"r"(a[1]),"r"(a[2]),"r"(a[3]), "r"(b0),"r"(b1));
}

__device__ __forceinline__ void cp_async16(uint32_t dst, const void* src){
  asm volatile("cp.async.cg.shared.global [%0], [%1], 16;" :: "r"(dst), "l"(src));
}
#define CP_COMMIT() asm volatile("cp.async.commit_group;" ::: "memory")
#define CP_WAIT2()  asm volatile("cp.async.wait_group 2;" ::: "memory")
#define CP_WAIT1()  asm volatile("cp.async.wait_group 1;" ::: "memory")
#define CP_WAIT0()  asm volatile("cp.async.wait_group 0;" ::: "memory")

// ---------------- weight fp16 prep ----------------
__global__ void prep_weights(const float* __restrict__ Wq, const float* __restrict__ Wk,
                             const float* __restrict__ Wv, const float* __restrict__ Wo){
  int i = blockIdx.x * blockDim.x + threadIdx.x;   // 0 .. 65535
  const float* src[4] = {Wq, Wk, Wv, Wo};
#pragma unroll
  for (int w = 0; w < 4; w++){
    g_Wf[w][i] = __float2half_rn(src[w][i]);
  }
}

// ============ PHASE 0: Q/K/V projections ======================================
// fp16 MMA, fp32 acc. CTA tile 128x256, 512 threads, 16 warps (64x32), BK=64,
// 4-STAGE cp.async pipeline (one unique stage per K-chunk, no stage reuse)
// + double-buffered register fragments + interleaved fp32->fp16 A convert.
// stage: A 128x64 (16K) + B 256x64 (32K) = 48KB; x4 = 192KB dynamic.
#define Q_ST_A 16384
#define Q_ST_B 32768
#define Q_STAGE (Q_ST_A + Q_ST_B)
#define Q_SMEM  (4*Q_STAGE)

__global__ void __launch_bounds__(512, 1)
gemm_qkv(const float* __restrict__ p, const float* __restrict__ c,
         const float* __restrict__ bq, const float* __restrict__ bk,
         const float* __restrict__ bv)
{
  extern __shared__ __align__(128) char smem[];

  const int job = (int)blockIdx.x;
  const float* __restrict__ Xf;
  const __half* __restrict__ Wm;
  __half* __restrict__ Yh;
  const float* __restrict__ bias;
  size_t mBase;
  if (job < 512){
    Xf = p;  Wm = g_Wf[0]; Yh = g_Qh; bias = bq; mBase = (size_t)job * 128;
  } else {
    const int j = job - 512;               // K/V adjacent per M-tile
    Xf = c;  mBase = (size_t)(j >> 1) * 128;
    if ((j & 1) == 0){ Wm = g_Wf[1]; Yh = g_Kh; bias = bk; }
    else             { Wm = g_Wf[2]; Yh = g_Vh; bias = bv; }
  }

  const int tid  = threadIdx.x;
  const int lane = tid & 31;
  const int warp = tid >> 5;         // 0..15
  const int wm   = warp & 1;         // rows wm*64
  const int wn   = warp >> 1;        // cols wn*32 (0..7)

  auto issueAsync = [&](int kk, int s){
    char* st = smem + s * Q_STAGE;
#pragma unroll
    for (int i = 0; i < 4; i++){
      int id = tid + i*512;                   // 0..2047
      int row = id >> 3, c8 = (id & 7) * 8;
      uint32_t d = (uint32_t)__cvta_generic_to_shared(st + Q_ST_A + swb(row*128 + c8*2));
      cp_async16(d, Wm + (size_t)row*E_DIM + kk + c8);
    }
    CP_COMMIT();
  };

  float4 ra[2];
  auto loadAh = [&](int kk, int h){
#pragma unroll
    for (int i = 0; i < 2; i++){
      int id = tid + i*512 + h*1024;
      int row = id >> 4, c4 = id & 15;
      ra[i] = *reinterpret_cast<const float4*>(Xf + (mBase + row)*E_DIM + kk + c4*4);
    }
  };
  auto storeAh = [&](int s, int h){
    char* st = smem + s * Q_STAGE;
#pragma unroll
    for (int i = 0; i < 2; i++){
      int id = tid + i*512 + h*1024;
      int row = id >> 4, c4 = id & 15;
      float4 v = ra[i];
      __half2 h0 = __float22half2_rn(make_float2(v.x, v.y));
      __half2 h1 = __float22half2_rn(make_float2(v.z, v.w));
      int b0 = swb(row*128 + c4*8);
      *reinterpret_cast<__half2*>(st + b0)     = h0;
      *reinterpret_cast<__half2*>(st + b0 + 4) = h1;
    }
  };

  auto ldsmA = [&](char* sAc, int ks, uint32_t Af[4][4]){
#pragma unroll
    for (int mt = 0; mt < 4; mt++){
      int row = wm*64 + mt*16 + (lane & 7) + ((lane & 8) ? 8 : 0);
      int col = ks + ((lane & 16) ? 8 : 0);
      ldm4((uint32_t)__cvta_generic_to_shared(sAc + swb(row*128 + col*2)), Af[mt]);
    }
  };
  auto ldsmB = [&](char* sBc, int ks, uint32_t Bf[2][4]){
#pragma unroll
    for (int bt = 0; bt < 2; bt++){
      int row = wn*32 + bt*16 + (lane & 7) + ((lane & 8) ? 8 : 0);
      int col = ks + ((lane & 16) ? 8 : 0);
      ldm4((uint32_t)__cvta_generic_to_shared(sBc + swb(row*128 + col*2)), Bf[bt]);
    }
  };

  float acc[4][4][4];   // warp 64x32: [mt][nt][4]
#pragma unroll
  for (int i=0;i<4;i++)
#pragma unroll
    for (int j=0;j<4;j++)
#pragma unroll
      for (int k=0;k<4;k++) acc[i][j][k] = 0.f;

  // prologue: B chunks 0,1,2 in flight; A chunk 0 staged
  issueAsync(0, 0);
  loadAh(0, 0); storeAh(0, 0);
  loadAh(0, 1); storeAh(0, 1);
  issueAsync(64, 1);
  issueAsync(128, 2);

  uint32_t Af[2][4][4], Bf[2][2][4];

  for (int kc = 0; kc < 4; kc++){
    if (kc <= 1) CP_WAIT2(); else if (kc == 2) CP_WAIT1(); else CP_WAIT0();
    __syncthreads();

    if (kc == 0) issueAsync(192, 3);
    const int ns = kc + 1;                   // unique A stage for next chunk
    const bool preA = (kc < 3);

    char* sAc = smem + kc * Q_STAGE;
    char* sBc = sAc + Q_ST_A;

    ldsmA(sAc, 0, Af[0]);
    ldsmB(sBc, 0, Bf[0]);
#pragma unroll
    for (int ks2 = 0; ks2 < 4; ks2++){
      const int cur = ks2 & 1, nxt = cur ^ 1;
      if (ks2 < 3){
        ldsmA(sAc, (ks2+1)*16, Af[nxt]);
        ldsmB(sBc, (ks2+1)*16, Bf[nxt]);
      }
#pragma unroll
      for (int mt=0; mt<4; mt++)
#pragma unroll
        for (int nt=0; nt<4; nt++){
          const int bt = nt >> 1, od = nt & 1;
          mma16816(acc[mt][nt], Af[cur][mt], Bf[cur][bt][od], Bf[cur][bt][2+od]);
        }
      if (preA){
        if      (ks2 == 0){ loadAh((kc+1)*64, 0); }
        else if (ks2 == 1){ storeAh(ns, 0); loadAh((kc+1)*64, 1); }
        else if (ks2 == 2){ storeAh(ns, 1); }
      }
    }
  }

  // epilogue: +bias, fp16 stores
#pragma unroll
  for (int mt=0; mt<4; mt++){
#pragma unroll
    for (int nt=0; nt<4; nt++){
      size_t m = mBase + wm*64 + mt*16 + (lane>>2);
      int    n = wn*32 + nt*8 + (lane&3)*2;
      float b0 = bias[n], b1 = bias[n+1];
      float* a = acc[mt][nt];
      *reinterpret_cast<__half2*>(Yh + m*E_DIM + n)     = __floats2half2_rn(a[0]+b0, a[1]+b1);
      *reinterpret_cast<__half2*>(Yh + (m+8)*E_DIM + n) = __floats2half2_rn(a[2]+b0, a[3]+b1);
    }
  }
}

// ============ PHASE 1 (measured-best, round 15): O GEMM ========================
// CTA tile 128x128, 8 warps (64x32), BK=64, 3-stage cp.async A+B pipeline,
// double-buffered register fragments. fp32 output stores.
#define O_ST_A 16384
#define O_STAGE (2*O_ST_A)
#define O_SMEM  (3*O_STAGE)

__global__ void __launch_bounds__(256, 1)
gemm_o(const float* __restrict__ bo, float* __restrict__ out)
{
  extern __shared__ __align__(128) char smem[];

  const int job = (int)blockIdx.x;
  const __half* __restrict__ Wm = g_Wf[3];
  const size_t mBase = (size_t)(job >> 1) * 128;
  const int    nBase = (job & 1) * 128;

  const int tid  = threadIdx.x;
  const int lane = tid & 31;
  const int warp = tid >> 5;
  const int wm   = warp & 1;        // rows wm*64
  const int wn   = warp >> 1;       // cols wn*32 (0..3)

  auto issueAsync = [&](int kk, int s){
    char* st = smem + s * O_STAGE;
#pragma unroll
    for (int i = 0; i < 4; i++){
      int id = tid + i*256;
      int row = id >> 3, c8 = (id & 7) * 8;
      uint32_t d = (uint32_t)__cvta_generic_to_shared(st + swb(row*128 + c8*2));
      cp_async16(d, g_WSh + (mBase + row)*E_DIM + kk + c8);
    }
#pragma unroll
    for (int i = 0; i < 4; i++){
      int id = tid + i*256;
      int row = id >> 3, c8 = (id & 7) * 8;
      uint32_t d = (uint32_t)__cvta_generic_to_shared(st + O_ST_A + swb(row*128 + c8*2));
      cp_async16(d, Wm + (size_t)(nBase + row)*E_DIM + kk + c8);
    }
    CP_COMMIT();
  };

  auto ldsmA = [&](char* sAc, int ks, uint32_t Af[4][4]){
#pragma unroll
    for (int mt = 0; mt < 4; mt++){
      int row = wm*64 + mt*16 + (lane & 7) + ((lane & 8) ? 8 : 0);
      int col = ks + ((lane & 16) ? 8 : 0);
      ldm4((uint32_t)__cvta_generic_to_shared(sAc + swb(row*128 + col*2)), Af[mt]);
    }
  };
  auto ldsmB = [&](char* sBc, int ks, uint32_t Bf[2][4]){
#pragma unroll
    for (int bt = 0; bt < 2; bt++){
      int row = wn*32 + bt*16 + (lane & 7) + ((lane & 8) ? 8 : 0);
      int col = ks + ((lane & 16) ? 8 : 0);
      ldm4((uint32_t)__cvta_generic_to_shared(sBc + swb(row*128 + col*2)), Bf[bt]);
    }
  };

  float acc[4][4][4];
#pragma unroll
  for (int i=0;i<4;i++)
#pragma unroll
    for (int j=0;j<4;j++)
#pragma unroll
      for (int k=0;k<4;k++) acc[i][j][k] = 0.f;

  issueAsync(0, 0);
  issueAsync(64, 1);

  uint32_t Af[2][4][4], Bf[2][2][4];

  for (int kc = 0; kc < 4; kc++){
    const int curS = kc % 3;
    if (kc < 3) CP_WAIT1(); else CP_WAIT0();
    __syncthreads();

    if (kc < 2) issueAsync((kc+2)*64, (kc+2) % 3);

    char* sAc = smem + curS * O_STAGE;
    char* sBc = sAc + O_ST_A;

    ldsmA(sAc, 0, Af[0]);
    ldsmB(sBc, 0, Bf[0]);
#pragma unroll
    for (int ks2 = 0; ks2 < 4; ks2++){
      const int cur = ks2 & 1, nxt = cur ^ 1;
      if (ks2 < 3){
        ldsmA(sAc, (ks2+1)*16, Af[nxt]);
        ldsmB(sBc, (ks2+1)*16, Bf[nxt]);
      }
#pragma unroll
      for (int mt=0; mt<4; mt++)
#pragma unroll
        for (int nt=0; nt<4; nt++){
          const int bt = nt >> 1, od = nt & 1;
          mma16816(acc[mt][nt], Af[cur][mt], Bf[cur][bt][od], Bf[cur][bt][2+od]);
        }
    }
  }

  // epilogue: +bias, fp32 stores
#pragma unroll
  for (int mt=0; mt<4; mt++){
#pragma unroll
    for (int nt=0; nt<4; nt++){
      size_t m = mBase + wm*64 + mt*16 + (lane>>2);
      int    n = nBase + wn*32 + nt*8 + (lane&3)*2;
      float b0 = bo[n], b1 = bo[n+1];
      float* a = acc[mt][nt];
      *reinterpret_cast<float2*>(out + m*E_DIM + n)     = make_float2(a[0]+b0, a[1]+b1);
      *reinterpret_cast<float2*>(out + (m+8)*E_DIM + n) = make_float2(a[2]+b0, a[3]+b1);
    }
  }
}

// ---------------- attention: warp per token, fp32 math on fp16 data ------------
__device__ __forceinline__ float dot8(uint4 a, uint4 b){
  const __half2* ah = reinterpret_cast<const __half2*>(&a);
  const __half2* bh = reinterpret_cast<const __half2*>(&b);
  float s = 0.f;
#pragma unroll
  for (int i = 0; i < 4; i++){
    float2 af = __half22float2(ah[i]);
    float2 bf = __half22float2(bh[i]);
    s += af.x*bf.x + af.y*bf.y;
  }
  return s;
}

__global__ void __launch_bounds__(256)
attn_kernel()
{
  const int gw   = (blockIdx.x * 256 + threadIdx.x) >> 5;  // token id
  const int lane = threadIdx.x & 31;                        // 8 lanes per head

  const uint4* q  = reinterpret_cast<const uint4*>(g_Qh + (size_t)gw*E_DIM);
  const uint4* k0 = reinterpret_cast<const uint4*>(g_Kh + (size_t)(2*gw  )*E_DIM);
  const uint4* k1 = reinterpret_cast<const uint4*>(g_Kh + (size_t)(2*gw+1)*E_DIM);
  const uint4* v0 = reinterpret_cast<const uint4*>(g_Vh + (size_t)(2*gw  )*E_DIM);
  const uint4* v1 = reinterpret_cast<const uint4*>(g_Vh + (size_t)(2*gw+1)*E_DIM);
  uint4*       ws = reinterpret_cast<uint4*>(g_WSh + (size_t)gw*E_DIM);

  uint4 qa = q[lane];
  float s0 = dot8(qa, k0[lane]);
  float s1 = dot8(qa, k1[lane]);

#pragma unroll
  for (int off = 4; off > 0; off >>= 1){            // reduce within 8-lane head group
    s0 += __shfl_xor_sync(0xffffffffu, s0, off);
    s1 += __shfl_xor_sync(0xffffffffu, s1, off);
  }
  s0 *= 0.125f;  s1 *= 0.125f;                       // 1/sqrt(D), D=64
  float mx = fmaxf(s0, s1);
  float e0 = __expf(s0 - mx), e1 = __expf(s1 - mx);
  float inv = 1.0f / (e0 + e1);
  float w0 = e0 * inv, w1 = e1 * inv;

  uint4 va = v0[lane], vb = v1[lane];
  const __half2* vah = reinterpret_cast<const __half2*>(&va);
  const __half2* vbh = reinterpret_cast<const __half2*>(&vb);
  uint4 o;
  __half2* oh = reinterpret_cast<__half2*>(&o);
#pragma unroll
  for (int i = 0; i < 4; i++){
    float2 a = __half22float2(vah[i]);
    float2 b = __half22float2(vbh[i]);
    oh[i] = __floats2half2_rn(w0*a.x + w1*b.x, w0*a.y + w1*b.y);
  }
  ws[lane] = o;
}

// ---------------- launch ----------------
extern "C" void kernel_launch(void* const* d_in, const int* in_sizes, int n_in,
                              void* d_out, int out_size)
{
  const float* p  = (const float*)d_in[0];  // (B,S,A,1,E)  -> [65536,256]
  const float* c  = (const float*)d_in[1];  // (B,S,A,2,E)  -> [131072,256]
  const float* Wq = (const float*)d_in[2];
  const float* bq = (const float*)d_in[3];
  const float* Wk = (const float*)d_in[4];
  const float* bk = (const float*)d_in[5];
  const float* Wv = (const float*)d_in[6];
  const float* bv = (const float*)d_in[7];
  const float* Wo = (const float*)d_in[8];
  const float* bo = (const float*)d_in[9];
  float* out = (float*)d_out;

  cudaFuncSetAttribute(gemm_qkv, cudaFuncAttributeMaxDynamicSharedMemorySize, Q_SMEM);
  cudaFuncSetAttribute(gemm_o,   cudaFuncAttributeMaxDynamicSharedMemorySize, O_SMEM);

  prep_weights<<<256, 256>>>(Wq, Wk, Wv, Wo);
  // merged Q/K/V: 512 Q jobs + 2048 KV jobs (128x256 tiles, 512 threads, 4-stage)
  gemm_qkv<<<2560, 512, Q_SMEM>>>(p, c, bq, bk, bv);
  attn_kernel<<<MQ/8, 256>>>();
  // out = WS @ Wo^T + bo (128x128 tiles, 256 threads, frag-double-buffered)
  gemm_o<<<1024, 256, O_SMEM>>>(bo, out);
}